// round 3
// baseline (speedup 1.0000x reference)
#include <cuda_runtime.h>
#include <cstdint>

// ---------------------------------------------------------------------------
// LargeLoss via radix-select on RAW INPUT BITS (softplus is monotone).
// 4 launches:
//   passA   : stream in+tg -> hist1(top 12 key bits) + compact candidate keys
//             last block: select stage0 (p1, k1, mode), zero hist2, pad keys
//   passB   : scan keys -> hist2(bits 19:8 where key>>20==p1) + compact match
//             last block: select stage1 (p2, k2), zero hist3, pad keys2
//   passC   : scan keys2 -> hist3(bits 7:0 where key>>8==p2)
//             last block: select stage2 -> g_thr
//   finalize: stream in+tg -> losses, mask negs by (loss < thr); re-zero state
// ---------------------------------------------------------------------------

#define N_MAX 10240008

__device__ unsigned g_keys[N_MAX];
__device__ unsigned g_keys2[N_MAX];
__device__ unsigned g_hist1[4096];
__device__ unsigned g_hist2[4096];
__device__ unsigned g_hist3[256];
__device__ unsigned g_cnt, g_cnt2;
__device__ unsigned g_k1, g_k2;
__device__ unsigned g_p1, g_p2;
__device__ int      g_mode;   // 0 normal, 1 keep-all (k==0), 2 drop-all (k > #cand)
__device__ float    g_thr;
__device__ unsigned g_doneA, g_doneB, g_doneC;

// ---------------------------------------------------------------------------
__device__ __forceinline__ unsigned f2key(float x) {
    unsigned b = __float_as_uint(x);
    return (b & 0x80000000u) ? ~b : (b | 0x80000000u);
}
__device__ __forceinline__ float key2f(unsigned k) {
    unsigned b = (k & 0x80000000u) ? (k & 0x7FFFFFFFu) : ~k;
    return __uint_as_float(b);
}
__device__ __forceinline__ float neg_loss_f(float x) {   // softplus(x)
    return fmaxf(x, 0.0f) + log1pf(expf(-fabsf(x)));
}

// ---------------------------------------------------------------------------
// Block-wide (256 threads) suffix-select: find bin b with suffix(b) >= k
// and suffix(b+1) < k over NB bins. Returns found/bin/krem/total to all.
template<int NB>
__device__ __forceinline__ void block_select_256(const unsigned* hist, unsigned k,
        unsigned& bin, unsigned& krem, unsigned& total, bool& found) {
    constexpr int PER = NB / 256;
    __shared__ unsigned wsum[8], wsuf[8];
    __shared__ unsigned s_bin, s_krem;
    const int tid = threadIdx.x;
    const int lane = tid & 31, wid = tid >> 5;

    unsigned h[PER]; unsigned s = 0;
#pragma unroll
    for (int j = 0; j < PER; j++) { h[j] = hist[tid * PER + j]; s += h[j]; }
    unsigned v = s;
#pragma unroll
    for (int d = 1; d < 32; d <<= 1) {
        unsigned u = __shfl_down_sync(0xffffffffu, v, d);
        if (lane + d < 32) v += u;
    }
    if (lane == 0) wsum[wid] = v;
    if (tid == 0) s_bin = 0xFFFFFFFFu;
    __syncthreads();
    if (tid < 8) {
        unsigned acc = 0;
        for (int j = tid + 1; j < 8; j++) acc += wsum[j];
        wsuf[tid] = acc;
    }
    __syncthreads();
    unsigned sfx = v + wsuf[wid];
    total = wsuf[0] + wsum[0];
    if (k != 0u) {
        unsigned run = sfx;
#pragma unroll
        for (int j = 0; j < PER; j++) {
            unsigned nxt = run - h[j];
            if (run >= k && nxt < k) { s_bin = (unsigned)(tid * PER + j); s_krem = k - nxt; }
            run = nxt;
        }
    }
    __syncthreads();
    found = (s_bin != 0xFFFFFFFFu);
    bin = found ? s_bin : 0u;
    krem = found ? s_krem : 0u;
}

// ---------------------------------------------------------------------------
__global__ void passA_kernel(const float* __restrict__ in,
                             const float* __restrict__ tg,
                             const int* __restrict__ kptr, int n) {
    __shared__ unsigned hist[4096];
    __shared__ unsigned stage[4096];
    __shared__ unsigned s_cnt, s_base;
    __shared__ int s_last;

    const int tid = threadIdx.x, bs = blockDim.x;
    const int lane = tid & 31;
    for (int i = tid; i < 4096; i += bs) hist[i] = 0u;
    if (tid == 0) s_cnt = 0u;
    __syncthreads();

    const float4* in4 = (const float4*)in;
    const float4* tg4 = (const float4*)tg;
    const int n4 = n >> 2;
    const int step = gridDim.x * bs * 2;

    for (int base = blockIdx.x * bs * 2; base < n4; base += step) {
        int i0 = base + tid;
        int i1 = base + bs + tid;
        bool v0 = i0 < n4, v1 = i1 < n4;
        float4 x0, t0, x1, t1;
        if (v0) { x0 = in4[i0]; t0 = tg4[i0]; }
        if (v1) { x1 = in4[i1]; t1 = tg4[i1]; }

        int c0 = v0 ? ((t0.x < 0.f) + (t0.y < 0.f) + (t0.z < 0.f) + (t0.w < 0.f)) : 0;
        int c1 = v1 ? ((t1.x < 0.f) + (t1.y < 0.f) + (t1.z < 0.f) + (t1.w < 0.f)) : 0;
        unsigned cnt = (unsigned)(c0 + c1);

        unsigned inc = cnt;
#pragma unroll
        for (int d = 1; d < 32; d <<= 1) {
            unsigned u = __shfl_up_sync(0xffffffffu, inc, d);
            if (lane >= d) inc += u;
        }
        unsigned wtot = __shfl_sync(0xffffffffu, inc, 31);
        unsigned wbase = 0;
        if (lane == 0 && wtot) wbase = atomicAdd(&s_cnt, wtot);
        wbase = __shfl_sync(0xffffffffu, wbase, 0);
        unsigned p = wbase + (inc - cnt);

#define PUSH(xv, tv) do { if ((tv) < 0.f) {                       \
            unsigned kk = f2key(xv);                              \
            atomicAdd(&hist[kk >> 20], 1u);                       \
            stage[p++] = kk; } } while (0)
        if (v0) { PUSH(x0.x, t0.x); PUSH(x0.y, t0.y); PUSH(x0.z, t0.z); PUSH(x0.w, t0.w); }
        if (v1) { PUSH(x1.x, t1.x); PUSH(x1.y, t1.y); PUSH(x1.z, t1.z); PUSH(x1.w, t1.w); }
#undef PUSH

        __syncthreads();
        unsigned c = s_cnt;
        if (c >= 2048u) {
            if (tid == 0) s_base = atomicAdd(&g_cnt, c);
            __syncthreads();
            unsigned gb = s_base;
            for (unsigned j = tid; j < c; j += bs) g_keys[gb + j] = stage[j];
            __syncthreads();
            if (tid == 0) s_cnt = 0u;
            __syncthreads();
        }
    }

    // scalar tail, block 0 only (uniform loop for warp ops)
    if (blockIdx.x == 0) {
        for (int base = (n >> 2) << 2; base < n; base += bs) {
            int i = base + tid;
            unsigned cnt = 0; unsigned kk = 0;
            if (i < n && tg[i] < 0.f) { kk = f2key(in[i]); cnt = 1; atomicAdd(&hist[kk >> 20], 1u); }
            unsigned inc = cnt;
#pragma unroll
            for (int d = 1; d < 32; d <<= 1) {
                unsigned u = __shfl_up_sync(0xffffffffu, inc, d);
                if (lane >= d) inc += u;
            }
            unsigned wtot = __shfl_sync(0xffffffffu, inc, 31);
            unsigned wbase = 0;
            if (lane == 0 && wtot) wbase = atomicAdd(&s_cnt, wtot);
            wbase = __shfl_sync(0xffffffffu, wbase, 0);
            if (cnt) stage[wbase + inc - 1] = kk;
        }
    }

    __syncthreads();
    unsigned c = s_cnt;
    if (c > 0u) {
        if (tid == 0) s_base = atomicAdd(&g_cnt, c);
        __syncthreads();
        unsigned gb = s_base;
        for (unsigned j = tid; j < c; j += bs) g_keys[gb + j] = stage[j];
    }
    __syncthreads();
    for (int i = tid; i < 4096; i += bs) {
        unsigned hv = hist[i];
        if (hv) atomicAdd(&g_hist1[i], hv);
    }

    // ---- fused select stage 0 (last block) ----
    __threadfence();
    __syncthreads();
    if (tid == 0) {
        unsigned t = atomicAdd(&g_doneA, 1u);
        s_last = (t == gridDim.x - 1);
    }
    __syncthreads();
    if (!s_last) return;

    int kraw = *kptr;
    unsigned k0 = (kraw > 0) ? (unsigned)kraw : 0u;
    unsigned bin, krem, total; bool found;
    block_select_256<4096>(g_hist1, k0, bin, krem, total, found);
    if (tid == 0) {
        g_mode = (k0 == 0u) ? 1 : (found ? 0 : 2);
        g_p1 = bin;
        g_k1 = krem;
        g_doneA = 0u;
    }
    for (int i = tid; i < 4096; i += bs) g_hist2[i] = 0u;
    // pad compacted keys to a multiple of 4 with non-matching sentinels
    unsigned cfin = g_cnt;
    unsigned pad = (4u - (cfin & 3u)) & 3u;
    if ((unsigned)tid < pad) g_keys[cfin + tid] = 0xFFFFFFFFu;
}

// ---------------------------------------------------------------------------
__global__ void passB_kernel() {
    __shared__ unsigned hist[4096];
    __shared__ int s_last;
    const int tid = threadIdx.x, bs = blockDim.x;
    const int lane = tid & 31;
    for (int i = tid; i < 4096; i += bs) hist[i] = 0u;
    __syncthreads();

    const int mode = g_mode;
    const unsigned p1 = g_p1;
    const unsigned cnt = g_cnt;
    const unsigned m4 = (cnt + 3u) >> 2;

    if (mode == 0) {
        const uint4* k4 = (const uint4*)g_keys;
        const unsigned S = gridDim.x * bs;
        const unsigned niter = (m4 + S - 1u) / S;
        unsigned i = blockIdx.x * bs + tid;
        for (unsigned it = 0; it < niter; ++it, i += S) {
            bool v = i < m4;
            uint4 u = v ? k4[i] : make_uint4(0xFFFFFFFFu, 0xFFFFFFFFu, 0xFFFFFFFFu, 0xFFFFFFFFu);
#define PROC(e) do {                                                          \
            bool m = ((e) >> 20) == p1;                                      \
            if (m) atomicAdd(&hist[((e) >> 8) & 0xFFFu], 1u);                \
            unsigned bal = __ballot_sync(0xffffffffu, m);                    \
            if (bal) {                                                       \
                unsigned base = 0;                                           \
                if (lane == 0) base = atomicAdd(&g_cnt2, (unsigned)__popc(bal)); \
                base = __shfl_sync(0xffffffffu, base, 0);                    \
                if (m) g_keys2[base + __popc(bal & ((1u << lane) - 1u))] = (e); \
            } } while (0)
            PROC(u.x); PROC(u.y); PROC(u.z); PROC(u.w);
#undef PROC
        }
        __syncthreads();
        for (int i2 = tid; i2 < 4096; i2 += bs) {
            unsigned hv = hist[i2];
            if (hv) atomicAdd(&g_hist2[i2], hv);
        }
    }

    __threadfence();
    __syncthreads();
    if (tid == 0) {
        unsigned t = atomicAdd(&g_doneB, 1u);
        s_last = (t == gridDim.x - 1);
    }
    __syncthreads();
    if (!s_last) return;

    unsigned k1 = (mode == 0) ? g_k1 : 0u;
    unsigned bin, krem, total; bool found;
    block_select_256<4096>(g_hist2, k1, bin, krem, total, found);
    if (tid == 0) {
        g_p2 = (p1 << 12) | bin;
        g_k2 = krem;
        g_doneB = 0u;
    }
    if (tid < 256) g_hist3[tid] = 0u;
    unsigned c2 = g_cnt2;
    unsigned pad = (4u - (c2 & 3u)) & 3u;
    if ((unsigned)tid < pad) g_keys2[c2 + tid] = 0xFFFFFFFFu;
}

// ---------------------------------------------------------------------------
__global__ void passC_kernel() {
    __shared__ unsigned hist[256];
    __shared__ int s_last;
    const int tid = threadIdx.x, bs = blockDim.x;
    if (tid < 256) hist[tid] = 0u;
    __syncthreads();

    const int mode = g_mode;
    const unsigned p2 = g_p2;
    const unsigned cnt2 = g_cnt2;
    const unsigned m4 = (cnt2 + 3u) >> 2;

    if (mode == 0) {
        const uint4* k4 = (const uint4*)g_keys2;
        const unsigned S = gridDim.x * bs;
        const unsigned niter = (m4 + S - 1u) / S;
        unsigned i = blockIdx.x * bs + tid;
        for (unsigned it = 0; it < niter; ++it, i += S) {
            if (i < m4) {
                uint4 u = k4[i];
                if ((u.x >> 8) == p2) atomicAdd(&hist[u.x & 0xFFu], 1u);
                if ((u.y >> 8) == p2) atomicAdd(&hist[u.y & 0xFFu], 1u);
                if ((u.z >> 8) == p2) atomicAdd(&hist[u.z & 0xFFu], 1u);
                if ((u.w >> 8) == p2) atomicAdd(&hist[u.w & 0xFFu], 1u);
            }
        }
        __syncthreads();
        if (tid < 256) {
            unsigned hv = hist[tid];
            if (hv) atomicAdd(&g_hist3[tid], hv);
        }
    }

    __threadfence();
    __syncthreads();
    if (tid == 0) {
        unsigned t = atomicAdd(&g_doneC, 1u);
        s_last = (t == gridDim.x - 1);
    }
    __syncthreads();
    if (!s_last) return;

    unsigned k2 = (mode == 0) ? g_k2 : 0u;
    unsigned bin, krem, total; bool found;
    block_select_256<256>(g_hist3, k2, bin, krem, total, found);
    if (tid == 0) {
        float thr;
        if (mode == 1)      thr = __int_as_float(0x7f800000);  // +inf: keep all
        else if (mode == 2) thr = 0.0f;                        // drop all negs
        else                thr = neg_loss_f(key2f((p2 << 8) | bin));
        g_thr = thr;
        g_doneC = 0u;
    }
}

// ---------------------------------------------------------------------------
__device__ __forceinline__ float elem_loss(float x, float t, float thr) {
    float ax  = fabsf(x);
    float lse = log1pf(expf(-ax));
    float pl  = fmaxf(-x, 0.0f) + lse;
    float nl  = fmaxf( x, 0.0f) + lse;
    float r = 0.0f;
    if (t > 0.0f) r = pl;
    else if (t < 0.0f) r = (nl < thr) ? nl : 0.0f;
    return r;
}

__global__ void finalize_kernel(const float* __restrict__ in,
                                const float* __restrict__ tg,
                                float* __restrict__ out, int n) {
    // re-zero selection state for the next graph replay
    if (blockIdx.x == gridDim.x - 1) {
        for (int i = threadIdx.x; i < 4096; i += blockDim.x) g_hist1[i] = 0u;
        if (threadIdx.x == 0) { g_cnt = 0u; g_cnt2 = 0u; }
    }

    const float thr = g_thr;
    const float4* in4 = (const float4*)in;
    const float4* tg4 = (const float4*)tg;
    float4* o4 = (float4*)out;
    const int n4 = n >> 2;
    const int S = gridDim.x * blockDim.x;
    int i = blockIdx.x * blockDim.x + threadIdx.x;

    for (; i + S < n4; i += 2 * S) {
        float4 x0 = in4[i], t0 = tg4[i];
        float4 x1 = in4[i + S], t1 = tg4[i + S];
        float4 o0, o1;
        o0.x = elem_loss(x0.x, t0.x, thr); o0.y = elem_loss(x0.y, t0.y, thr);
        o0.z = elem_loss(x0.z, t0.z, thr); o0.w = elem_loss(x0.w, t0.w, thr);
        o1.x = elem_loss(x1.x, t1.x, thr); o1.y = elem_loss(x1.y, t1.y, thr);
        o1.z = elem_loss(x1.z, t1.z, thr); o1.w = elem_loss(x1.w, t1.w, thr);
        o4[i] = o0;
        o4[i + S] = o1;
    }
    for (; i < n4; i += S) {
        float4 x0 = in4[i], t0 = tg4[i];
        float4 o0;
        o0.x = elem_loss(x0.x, t0.x, thr); o0.y = elem_loss(x0.y, t0.y, thr);
        o0.z = elem_loss(x0.z, t0.z, thr); o0.w = elem_loss(x0.w, t0.w, thr);
        o4[i] = o0;
    }
    if (blockIdx.x == 0) {
        for (int j = (n4 << 2) + threadIdx.x; j < n; j += blockDim.x)
            out[j] = elem_loss(in[j], tg[j], thr);
    }
}

// ---------------------------------------------------------------------------
extern "C" void kernel_launch(void* const* d_in, const int* in_sizes, int n_in,
                              void* d_out, int out_size) {
    const float* inp  = (const float*)d_in[0];
    const float* tgt  = (const float*)d_in[1];
    const int*   kptr = (const int*)d_in[2];
    float* out = (float*)d_out;
    const int n = in_sizes[0];

    passA_kernel<<<1184, 256>>>(inp, tgt, kptr, n);
    passB_kernel<<<1184, 256>>>();
    passC_kernel<<<296, 256>>>();
    finalize_kernel<<<1184, 256>>>(inp, tgt, out, n);
}

// round 4
// speedup vs baseline: 1.3113x; 1.3113x over previous
#include <cuda_runtime.h>
#include <cstdint>

// ---------------------------------------------------------------------------
// LargeLoss via radix-select on RAW INPUT BITS (softplus is monotone, so the
// kth-largest unobserved loss == softplus(kth-largest x among t<0)).
// 8 launches (R2 skeleton):
//   init     : zero hist1, counters, load k
//   passA    : stream in+tg -> hist1 (top 12 key bits) + compact candidate
//              keys (shared-staged) + 2-bit class code per element
//   select 0 : pick 12-bit bucket p1, residual rank k1, mode; zero hist2
//   passB    : scan compacted keys -> hist2 (bits 19:8 where key>>20==p1)
//              + shared-staged compaction of matches into g_keys2
//   select 1 : pick 24-bit prefix p2, residual k2; zero hist3
//   passC    : scan g_keys2 -> hist3 (bits 7:0 where key>>8==p2)
//   select 2 : exact kth key -> g_thr = softplus(decode(key))
//   finalize : stream in + class codes -> losses, mask negs by (loss < thr)
// ---------------------------------------------------------------------------

#define N_MAX 10240000

__device__ unsigned g_keys[N_MAX];
__device__ unsigned g_keys2[N_MAX];
__device__ unsigned char g_code[N_MAX / 4 + 8];   // 2 bits/elem, 1 byte per float4
__device__ unsigned g_hist1[4096];
__device__ unsigned g_hist2[4096];
__device__ unsigned g_hist3[256];
__device__ unsigned g_cnt, g_cnt2;
__device__ unsigned g_k0, g_k1, g_k2;
__device__ unsigned g_p1, g_p2;
__device__ int      g_mode;   // 0 normal, 1 keep-all (k==0), 2 drop-all
__device__ float    g_thr;

// ---------------------------------------------------------------------------
__device__ __forceinline__ unsigned f2key(float x) {
    unsigned b = __float_as_uint(x);
    return (b & 0x80000000u) ? ~b : (b | 0x80000000u);
}
__device__ __forceinline__ float key2f(unsigned k) {
    unsigned b = (k & 0x80000000u) ? (k & 0x7FFFFFFFu) : ~k;
    return __uint_as_float(b);
}
__device__ __forceinline__ float neg_loss_f(float x) {   // softplus(x)
    return fmaxf(x, 0.0f) + log1pf(expf(-fabsf(x)));
}

// ---------------------------------------------------------------------------
__global__ void init_kernel(const int* __restrict__ kin) {
    int t = threadIdx.x;
    for (int i = t; i < 4096; i += blockDim.x) g_hist1[i] = 0u;
    if (t == 0) {
        g_cnt = 0u; g_cnt2 = 0u;
        int k = *kin;
        g_k0 = (k > 0) ? (unsigned)k : 0u;
    }
}

// ---------------------------------------------------------------------------
// Pass A: histogram (bits 31:20 of key), candidate key compaction, class code.
__global__ void passA_kernel(const float* __restrict__ in,
                             const float* __restrict__ tg, int n) {
    __shared__ unsigned hist[4096];
    __shared__ unsigned stage[4096];
    __shared__ unsigned s_cnt, s_base;

    const int tid = threadIdx.x, bs = blockDim.x;
    const int lane = tid & 31;
    for (int i = tid; i < 4096; i += bs) hist[i] = 0u;
    if (tid == 0) s_cnt = 0u;
    __syncthreads();

    const float4* in4 = (const float4*)in;
    const float4* tg4 = (const float4*)tg;
    const int n4 = n >> 2;
    const int step = gridDim.x * bs * 2;

    for (int base = blockIdx.x * bs * 2; base < n4; base += step) {
        int i0 = base + tid;
        int i1 = base + bs + tid;
        bool v0 = i0 < n4, v1 = i1 < n4;
        float4 x0, t0, x1, t1;
        if (v0) { x0 = in4[i0]; t0 = tg4[i0]; }
        if (v1) { x1 = in4[i1]; t1 = tg4[i1]; }

        // class per lane: 0 unobserved, 1 positive, 2 negative
        unsigned cls0 = 0, cls1 = 0;
        int c0 = 0, c1 = 0;
        if (v0) {
            unsigned a = (t0.x > 0.f) ? 1u : ((t0.x < 0.f) ? 2u : 0u);
            unsigned b = (t0.y > 0.f) ? 1u : ((t0.y < 0.f) ? 2u : 0u);
            unsigned c = (t0.z > 0.f) ? 1u : ((t0.z < 0.f) ? 2u : 0u);
            unsigned d = (t0.w > 0.f) ? 1u : ((t0.w < 0.f) ? 2u : 0u);
            cls0 = a | (b << 2) | (c << 4) | (d << 6);
            c0 = (a == 2u) + (b == 2u) + (c == 2u) + (d == 2u);
            g_code[i0] = (unsigned char)cls0;
        }
        if (v1) {
            unsigned a = (t1.x > 0.f) ? 1u : ((t1.x < 0.f) ? 2u : 0u);
            unsigned b = (t1.y > 0.f) ? 1u : ((t1.y < 0.f) ? 2u : 0u);
            unsigned c = (t1.z > 0.f) ? 1u : ((t1.z < 0.f) ? 2u : 0u);
            unsigned d = (t1.w > 0.f) ? 1u : ((t1.w < 0.f) ? 2u : 0u);
            cls1 = a | (b << 2) | (c << 4) | (d << 6);
            c1 = (a == 2u) + (b == 2u) + (c == 2u) + (d == 2u);
            g_code[i1] = (unsigned char)cls1;
        }
        unsigned cnt = (unsigned)(c0 + c1);

        unsigned inc = cnt;
#pragma unroll
        for (int d = 1; d < 32; d <<= 1) {
            unsigned u = __shfl_up_sync(0xffffffffu, inc, d);
            if (lane >= d) inc += u;
        }
        unsigned wtot = __shfl_sync(0xffffffffu, inc, 31);
        unsigned wbase = 0;
        if (lane == 0 && wtot) wbase = atomicAdd(&s_cnt, wtot);
        wbase = __shfl_sync(0xffffffffu, wbase, 0);
        unsigned p = wbase + (inc - cnt);

#define PUSH(xv, tv) do { if ((tv) < 0.f) {                       \
            unsigned kk = f2key(xv);                              \
            atomicAdd(&hist[kk >> 20], 1u);                       \
            stage[p++] = kk; } } while (0)
        if (v0) { PUSH(x0.x, t0.x); PUSH(x0.y, t0.y); PUSH(x0.z, t0.z); PUSH(x0.w, t0.w); }
        if (v1) { PUSH(x1.x, t1.x); PUSH(x1.y, t1.y); PUSH(x1.z, t1.z); PUSH(x1.w, t1.w); }
#undef PUSH

        __syncthreads();
        unsigned c = s_cnt;
        if (c >= 2048u) {
            if (tid == 0) s_base = atomicAdd(&g_cnt, c);
            __syncthreads();
            unsigned gb = s_base;
            for (unsigned j = tid; j < c; j += bs) g_keys[gb + j] = stage[j];
            __syncthreads();
            if (tid == 0) s_cnt = 0u;
            __syncthreads();
        }
    }

    // scalar tail (n % 4), block 0 only — uniform loop for warp ops
    if (blockIdx.x == 0) {
        for (int base = (n >> 2) << 2; base < n; base += bs) {
            int i = base + tid;
            unsigned cnt = 0; unsigned kk = 0;
            if (i < n && tg[i] < 0.f) { kk = f2key(in[i]); cnt = 1; atomicAdd(&hist[kk >> 20], 1u); }
            unsigned inc = cnt;
#pragma unroll
            for (int d = 1; d < 32; d <<= 1) {
                unsigned u = __shfl_up_sync(0xffffffffu, inc, d);
                if (lane >= d) inc += u;
            }
            unsigned wtot = __shfl_sync(0xffffffffu, inc, 31);
            unsigned wbase = 0;
            if (lane == 0 && wtot) wbase = atomicAdd(&s_cnt, wtot);
            wbase = __shfl_sync(0xffffffffu, wbase, 0);
            if (cnt) stage[wbase + inc - 1] = kk;
        }
    }

    __syncthreads();
    unsigned c = s_cnt;
    if (c > 0u) {
        if (tid == 0) s_base = atomicAdd(&g_cnt, c);
        __syncthreads();
        unsigned gb = s_base;
        for (unsigned j = tid; j < c; j += bs) g_keys[gb + j] = stage[j];
    }
    __syncthreads();
    for (int i = tid; i < 4096; i += bs) {
        unsigned hv = hist[i];
        if (hv) atomicAdd(&g_hist1[i], hv);
    }
}

// ---------------------------------------------------------------------------
// Pass B: hist2 (bits 19:8 where key>>20==p1) + shared-staged compaction of
// matching keys into g_keys2. Uniform trip count so __syncthreads is safe.
__global__ void passB_kernel() {
    __shared__ unsigned hist[4096];
    __shared__ unsigned stage[4096];
    __shared__ unsigned s_cnt, s_base;

    const int tid = threadIdx.x, bs = blockDim.x;
    const int lane = tid & 31;
    for (int i = tid; i < 4096; i += bs) hist[i] = 0u;
    if (tid == 0) s_cnt = 0u;
    __syncthreads();

    const unsigned p1  = g_p1;
    const unsigned cnt = g_cnt;
    const unsigned m4  = cnt >> 2;
    const uint4* k4 = (const uint4*)g_keys;
    const unsigned S = gridDim.x * bs;
    const unsigned niter = (m4 + S - 1u) / S;
    unsigned i = blockIdx.x * bs + tid;

    for (unsigned it = 0; it < niter; ++it, i += S) {
        bool v = i < m4;
        uint4 u = v ? k4[i] : make_uint4(0xFFFFFFFFu, 0xFFFFFFFFu, 0xFFFFFFFFu, 0xFFFFFFFFu);
        bool m0 = (u.x >> 20) == p1, m1 = (u.y >> 20) == p1;
        bool m2 = (u.z >> 20) == p1, m3 = (u.w >> 20) == p1;
        if (m0) atomicAdd(&hist[(u.x >> 8) & 0xFFFu], 1u);
        if (m1) atomicAdd(&hist[(u.y >> 8) & 0xFFFu], 1u);
        if (m2) atomicAdd(&hist[(u.z >> 8) & 0xFFFu], 1u);
        if (m3) atomicAdd(&hist[(u.w >> 8) & 0xFFFu], 1u);

        unsigned c = (unsigned)(m0 + m1 + m2 + m3);
        unsigned inc = c;
#pragma unroll
        for (int d = 1; d < 32; d <<= 1) {
            unsigned uu = __shfl_up_sync(0xffffffffu, inc, d);
            if (lane >= d) inc += uu;
        }
        unsigned wtot = __shfl_sync(0xffffffffu, inc, 31);
        unsigned wbase = 0;
        if (lane == 0 && wtot) wbase = atomicAdd(&s_cnt, wtot);
        wbase = __shfl_sync(0xffffffffu, wbase, 0);
        unsigned p = wbase + (inc - c);
        if (m0) stage[p++] = u.x;
        if (m1) stage[p++] = u.y;
        if (m2) stage[p++] = u.z;
        if (m3) stage[p++] = u.w;

        __syncthreads();
        unsigned sc = s_cnt;
        if (sc >= 2048u) {
            if (tid == 0) s_base = atomicAdd(&g_cnt2, sc);
            __syncthreads();
            unsigned gb = s_base;
            for (unsigned j = tid; j < sc; j += bs) g_keys2[gb + j] = stage[j];
            __syncthreads();
            if (tid == 0) s_cnt = 0u;
            __syncthreads();
        }
    }

    // scalar tail (cnt % 4), block 0 only — uniform loop
    if (blockIdx.x == 0) {
        for (unsigned base = m4 << 2; base < cnt; base += bs) {
            unsigned j = base + tid;
            unsigned c = 0; unsigned kk = 0;
            if (j < cnt) {
                kk = g_keys[j];
                if ((kk >> 20) == p1) { c = 1; atomicAdd(&hist[(kk >> 8) & 0xFFFu], 1u); }
            }
            unsigned inc = c;
#pragma unroll
            for (int d = 1; d < 32; d <<= 1) {
                unsigned uu = __shfl_up_sync(0xffffffffu, inc, d);
                if (lane >= d) inc += uu;
            }
            unsigned wtot = __shfl_sync(0xffffffffu, inc, 31);
            unsigned wbase = 0;
            if (lane == 0 && wtot) wbase = atomicAdd(&s_cnt, wtot);
            wbase = __shfl_sync(0xffffffffu, wbase, 0);
            if (c) stage[wbase + inc - 1] = kk;
        }
    }

    __syncthreads();
    unsigned sc = s_cnt;
    if (sc > 0u) {
        if (tid == 0) s_base = atomicAdd(&g_cnt2, sc);
        __syncthreads();
        unsigned gb = s_base;
        for (unsigned j = tid; j < sc; j += bs) g_keys2[gb + j] = stage[j];
    }
    __syncthreads();
    for (int i2 = tid; i2 < 4096; i2 += bs) {
        unsigned hv = hist[i2];
        if (hv) atomicAdd(&g_hist2[i2], hv);
    }
}

// ---------------------------------------------------------------------------
// Pass C: hist3 (bits 7:0 where key>>8==p2) over the small compacted set.
__global__ void passC_kernel() {
    __shared__ unsigned hist[256];
    const int tid = threadIdx.x, bs = blockDim.x;
    if (tid < 256) hist[tid] = 0u;
    __syncthreads();

    const unsigned p2 = g_p2;
    const unsigned cnt2 = g_cnt2;
    const unsigned m4 = cnt2 >> 2;
    const uint4* k4 = (const uint4*)g_keys2;
    const unsigned S = gridDim.x * bs;
    for (unsigned i = blockIdx.x * bs + tid; i < m4; i += S) {
        uint4 u = k4[i];
        if ((u.x >> 8) == p2) atomicAdd(&hist[u.x & 0xFFu], 1u);
        if ((u.y >> 8) == p2) atomicAdd(&hist[u.y & 0xFFu], 1u);
        if ((u.z >> 8) == p2) atomicAdd(&hist[u.z & 0xFFu], 1u);
        if ((u.w >> 8) == p2) atomicAdd(&hist[u.w & 0xFFu], 1u);
    }
    if (blockIdx.x == 0) {
        for (unsigned j = (m4 << 2) + tid; j < cnt2; j += bs) {
            unsigned u = g_keys2[j];
            if ((u >> 8) == p2) atomicAdd(&hist[u & 0xFFu], 1u);
        }
    }
    __syncthreads();
    if (tid < 256) {
        unsigned hv = hist[tid];
        if (hv) atomicAdd(&g_hist3[tid], hv);
    }
}

// ---------------------------------------------------------------------------
// Single-block select (1024 threads, 4 bins each): suffix sums + rank locate.
__global__ void select_kernel(int stage) {
    __shared__ unsigned smW[32];
    __shared__ unsigned smE[32];
    __shared__ unsigned sTotal;

    const int tid  = threadIdx.x;
    const int lane = tid & 31;
    const int wid  = tid >> 5;

    const unsigned* hist = (stage == 0) ? g_hist1 : (stage == 1) ? g_hist2 : g_hist3;
    const int nbins      = (stage == 2) ? 256 : 4096;

    unsigned h0 = 0, h1 = 0, h2 = 0, h3 = 0;
    int b0 = tid * 4;
    if (b0 + 0 < nbins) h0 = hist[b0 + 0];
    if (b0 + 1 < nbins) h1 = hist[b0 + 1];
    if (b0 + 2 < nbins) h2 = hist[b0 + 2];
    if (b0 + 3 < nbins) h3 = hist[b0 + 3];
    unsigned s = h0 + h1 + h2 + h3;

    unsigned v = s;
#pragma unroll
    for (int d = 1; d < 32; d <<= 1) {
        unsigned u = __shfl_down_sync(0xffffffffu, v, d);
        if (lane + d < 32) v += u;
    }
    if (lane == 0) smW[wid] = v;
    __syncthreads();
    if (wid == 0) {
        unsigned wv = smW[lane];
        unsigned wi = wv;
#pragma unroll
        for (int d = 1; d < 32; d <<= 1) {
            unsigned u = __shfl_down_sync(0xffffffffu, wi, d);
            if (lane + d < 32) wi += u;
        }
        smE[lane] = wi - wv;
        if (lane == 0) sTotal = wi;
    }
    __syncthreads();
    unsigned sfx = v + smE[wid];

    if (tid == 0) {
        if (stage == 0) {
            unsigned kk = g_k0;
            g_mode = (kk == 0u) ? 1 : (kk > sTotal ? 2 : 0);
            g_p1 = 0u; g_k1 = 0u;
        } else if (stage == 1) {
            g_p2 = 0u; g_k2 = 0u;
        } else {
            int m = g_mode;
            if (m == 1) g_thr = __int_as_float(0x7f800000);  // +inf: keep all
            else if (m == 2) g_thr = 0.0f;                   // drop all negs
        }
    }
    if (stage == 0) { for (int i = tid; i < 4096; i += blockDim.x) g_hist2[i] = 0u; }
    if (stage == 1) { if (tid < 256) g_hist3[tid] = 0u; }
    __syncthreads();

    int mode = g_mode;
    if (stage == 0) mode = (g_k0 == 0u) ? 1 : (g_k0 > sTotal ? 2 : 0);
    unsigned kk = (stage == 0) ? g_k0 : (stage == 1) ? g_k1 : g_k2;
    if (mode != 0 || kk == 0u) return;

    unsigned run = sfx;
    unsigned hh[4] = {h0, h1, h2, h3};
#pragma unroll
    for (int j = 0; j < 4; j++) {
        int bin = b0 + j;
        if (bin < nbins) {
            unsigned next = run - hh[j];
            if (run >= kk && next < kk) {
                if (stage == 0)      { g_p1 = (unsigned)bin;                g_k1 = kk - next; }
                else if (stage == 1) { g_p2 = (g_p1 << 12) | (unsigned)bin; g_k2 = kk - next; }
                else {
                    unsigned key = (g_p2 << 8) | (unsigned)bin;
                    g_thr = neg_loss_f(key2f(key));
                }
            }
            run = next;
        }
    }
}

// ---------------------------------------------------------------------------
__device__ __forceinline__ float lane_loss(float x, unsigned cls, float thr) {
    float ax  = fabsf(x);
    float lse = log1pf(expf(-ax));
    float pl  = fmaxf(-x, 0.0f) + lse;
    float nl  = fmaxf( x, 0.0f) + lse;
    float r = 0.0f;
    if (cls == 1u) r = pl;
    else if (cls == 2u) r = (nl < thr) ? nl : 0.0f;
    return r;
}
__device__ __forceinline__ float elem_loss_t(float x, float t, float thr) {
    unsigned cls = (t > 0.f) ? 1u : ((t < 0.f) ? 2u : 0u);
    return lane_loss(x, cls, thr);
}

__global__ void finalize_kernel(const float* __restrict__ in,
                                const float* __restrict__ tg,
                                float* __restrict__ out, int n) {
    const float thr = g_thr;
    const float4* in4 = (const float4*)in;
    float4* o4 = (float4*)out;
    const int n4 = n >> 2;
    const int S = gridDim.x * blockDim.x;
    int i = blockIdx.x * blockDim.x + threadIdx.x;

    for (; i + S < n4; i += 2 * S) {
        float4 x0 = in4[i];
        float4 x1 = in4[i + S];
        unsigned c0 = g_code[i];
        unsigned c1 = g_code[i + S];
        float4 o0, o1;
        o0.x = lane_loss(x0.x,  c0        & 3u, thr);
        o0.y = lane_loss(x0.y, (c0 >> 2)  & 3u, thr);
        o0.z = lane_loss(x0.z, (c0 >> 4)  & 3u, thr);
        o0.w = lane_loss(x0.w, (c0 >> 6)  & 3u, thr);
        o1.x = lane_loss(x1.x,  c1        & 3u, thr);
        o1.y = lane_loss(x1.y, (c1 >> 2)  & 3u, thr);
        o1.z = lane_loss(x1.z, (c1 >> 4)  & 3u, thr);
        o1.w = lane_loss(x1.w, (c1 >> 6)  & 3u, thr);
        o4[i] = o0;
        o4[i + S] = o1;
    }
    for (; i < n4; i += S) {
        float4 x0 = in4[i];
        unsigned c0 = g_code[i];
        float4 o0;
        o0.x = lane_loss(x0.x,  c0        & 3u, thr);
        o0.y = lane_loss(x0.y, (c0 >> 2)  & 3u, thr);
        o0.z = lane_loss(x0.z, (c0 >> 4)  & 3u, thr);
        o0.w = lane_loss(x0.w, (c0 >> 6)  & 3u, thr);
        o4[i] = o0;
    }
    if (blockIdx.x == 0) {
        for (int j = (n4 << 2) + threadIdx.x; j < n; j += blockDim.x)
            out[j] = elem_loss_t(in[j], tg[j], thr);
    }
}

// ---------------------------------------------------------------------------
extern "C" void kernel_launch(void* const* d_in, const int* in_sizes, int n_in,
                              void* d_out, int out_size) {
    const float* inp  = (const float*)d_in[0];
    const float* tgt  = (const float*)d_in[1];
    const int*   kptr = (const int*)d_in[2];
    float* out = (float*)d_out;
    const int n = in_sizes[0];

    init_kernel<<<1, 1024>>>(kptr);
    passA_kernel<<<1184, 256>>>(inp, tgt, n);
    select_kernel<<<1, 1024>>>(0);
    passB_kernel<<<1184, 256>>>();
    select_kernel<<<1, 1024>>>(1);
    passC_kernel<<<148, 256>>>();
    select_kernel<<<1, 1024>>>(2);
    finalize_kernel<<<1184, 256>>>(inp, tgt, out, n);
}

// round 5
// speedup vs baseline: 1.3967x; 1.0652x over previous
#include <cuda_runtime.h>
#include <cstdint>

// ---------------------------------------------------------------------------
// LargeLoss via radix-select on RAW INPUT BITS (softplus is monotone, so the
// kth-largest unobserved loss == softplus(kth-largest x among t<0)).
// R5 = R2 skeleton + full-grid refinement passes + class-code finalize.
//   init     : zero hist1, load k
//   passA    : stream in+tg -> hist1 (top 12 key bits) + compact candidate
//              keys (shared-staged) + 2-bit class code per element
//   select 0 : pick 12-bit bucket p1, residual rank k1, mode; zero hist2
//   passB    : plain scan of keys -> hist2 (bits 19:8 where key>>20==p1)
//   select 1 : pick 24-bit prefix p2, residual k2; zero hist3
//   passC    : plain scan of keys -> hist3 (bits 7:0 where key>>8==p2)
//   select 2 : exact kth key -> g_thr = softplus(decode(key))
//   finalize : stream in + class codes -> losses, mask negs by (loss < thr)
// ---------------------------------------------------------------------------

#define N_MAX 10240000

__device__ unsigned g_keys[N_MAX];
__device__ unsigned char g_code[N_MAX / 4 + 8];   // 2 bits/elem, 1 byte per float4
__device__ unsigned g_hist1[4096];
__device__ unsigned g_hist2[4096];
__device__ unsigned g_hist3[256];
__device__ unsigned g_cnt;
__device__ unsigned g_k0, g_k1, g_k2;
__device__ unsigned g_p1, g_p2;
__device__ int      g_mode;   // 0 normal, 1 keep-all (k==0), 2 drop-all
__device__ float    g_thr;

// ---------------------------------------------------------------------------
__device__ __forceinline__ unsigned f2key(float x) {
    unsigned b = __float_as_uint(x);
    return (b & 0x80000000u) ? ~b : (b | 0x80000000u);
}
__device__ __forceinline__ float key2f(unsigned k) {
    unsigned b = (k & 0x80000000u) ? (k & 0x7FFFFFFFu) : ~k;
    return __uint_as_float(b);
}
__device__ __forceinline__ float neg_loss_f(float x) {   // softplus(x)
    return fmaxf(x, 0.0f) + log1pf(expf(-fabsf(x)));
}

// ---------------------------------------------------------------------------
__global__ void init_kernel(const int* __restrict__ kin) {
    int t = threadIdx.x;
    for (int i = t; i < 4096; i += blockDim.x) g_hist1[i] = 0u;
    if (t == 0) {
        g_cnt = 0u;
        int k = *kin;
        g_k0 = (k > 0) ? (unsigned)k : 0u;
    }
}

// ---------------------------------------------------------------------------
// Pass A: histogram (bits 31:20 of key), candidate key compaction, class code.
__global__ void passA_kernel(const float* __restrict__ in,
                             const float* __restrict__ tg, int n) {
    __shared__ unsigned hist[4096];
    __shared__ unsigned stage[4096];
    __shared__ unsigned s_cnt, s_base;

    const int tid = threadIdx.x, bs = blockDim.x;
    const int lane = tid & 31;
    for (int i = tid; i < 4096; i += bs) hist[i] = 0u;
    if (tid == 0) s_cnt = 0u;
    __syncthreads();

    const float4* in4 = (const float4*)in;
    const float4* tg4 = (const float4*)tg;
    const int n4 = n >> 2;
    const int step = gridDim.x * bs * 2;

    for (int base = blockIdx.x * bs * 2; base < n4; base += step) {
        int i0 = base + tid;
        int i1 = base + bs + tid;
        bool v0 = i0 < n4, v1 = i1 < n4;
        float4 x0, t0, x1, t1;
        if (v0) { x0 = in4[i0]; t0 = tg4[i0]; }
        if (v1) { x1 = in4[i1]; t1 = tg4[i1]; }

        // class per lane: 0 unobserved, 1 positive, 2 negative
        int c0 = 0, c1 = 0;
        if (v0) {
            unsigned a = (t0.x > 0.f) ? 1u : ((t0.x < 0.f) ? 2u : 0u);
            unsigned b = (t0.y > 0.f) ? 1u : ((t0.y < 0.f) ? 2u : 0u);
            unsigned c = (t0.z > 0.f) ? 1u : ((t0.z < 0.f) ? 2u : 0u);
            unsigned d = (t0.w > 0.f) ? 1u : ((t0.w < 0.f) ? 2u : 0u);
            g_code[i0] = (unsigned char)(a | (b << 2) | (c << 4) | (d << 6));
            c0 = (a == 2u) + (b == 2u) + (c == 2u) + (d == 2u);
        }
        if (v1) {
            unsigned a = (t1.x > 0.f) ? 1u : ((t1.x < 0.f) ? 2u : 0u);
            unsigned b = (t1.y > 0.f) ? 1u : ((t1.y < 0.f) ? 2u : 0u);
            unsigned c = (t1.z > 0.f) ? 1u : ((t1.z < 0.f) ? 2u : 0u);
            unsigned d = (t1.w > 0.f) ? 1u : ((t1.w < 0.f) ? 2u : 0u);
            g_code[i1] = (unsigned char)(a | (b << 2) | (c << 4) | (d << 6));
            c1 = (a == 2u) + (b == 2u) + (c == 2u) + (d == 2u);
        }
        unsigned cnt = (unsigned)(c0 + c1);

        unsigned inc = cnt;
#pragma unroll
        for (int d = 1; d < 32; d <<= 1) {
            unsigned u = __shfl_up_sync(0xffffffffu, inc, d);
            if (lane >= d) inc += u;
        }
        unsigned wtot = __shfl_sync(0xffffffffu, inc, 31);
        unsigned wbase = 0;
        if (lane == 0 && wtot) wbase = atomicAdd(&s_cnt, wtot);
        wbase = __shfl_sync(0xffffffffu, wbase, 0);
        unsigned p = wbase + (inc - cnt);

#define PUSH(xv, tv) do { if ((tv) < 0.f) {                       \
            unsigned kk = f2key(xv);                              \
            atomicAdd(&hist[kk >> 20], 1u);                       \
            stage[p++] = kk; } } while (0)
        if (v0) { PUSH(x0.x, t0.x); PUSH(x0.y, t0.y); PUSH(x0.z, t0.z); PUSH(x0.w, t0.w); }
        if (v1) { PUSH(x1.x, t1.x); PUSH(x1.y, t1.y); PUSH(x1.z, t1.z); PUSH(x1.w, t1.w); }
#undef PUSH

        __syncthreads();
        unsigned c = s_cnt;
        if (c >= 2048u) {
            if (tid == 0) s_base = atomicAdd(&g_cnt, c);
            __syncthreads();
            unsigned gb = s_base;
            for (unsigned j = tid; j < c; j += bs) g_keys[gb + j] = stage[j];
            __syncthreads();
            if (tid == 0) s_cnt = 0u;
            __syncthreads();
        }
    }

    // scalar tail (n % 4), block 0 only — uniform loop for warp ops
    if (blockIdx.x == 0) {
        for (int base = (n >> 2) << 2; base < n; base += bs) {
            int i = base + tid;
            unsigned cnt = 0; unsigned kk = 0;
            if (i < n && tg[i] < 0.f) { kk = f2key(in[i]); cnt = 1; atomicAdd(&hist[kk >> 20], 1u); }
            unsigned inc = cnt;
#pragma unroll
            for (int d = 1; d < 32; d <<= 1) {
                unsigned u = __shfl_up_sync(0xffffffffu, inc, d);
                if (lane >= d) inc += u;
            }
            unsigned wtot = __shfl_sync(0xffffffffu, inc, 31);
            unsigned wbase = 0;
            if (lane == 0 && wtot) wbase = atomicAdd(&s_cnt, wtot);
            wbase = __shfl_sync(0xffffffffu, wbase, 0);
            if (cnt) stage[wbase + inc - 1] = kk;
        }
    }

    __syncthreads();
    unsigned c = s_cnt;
    if (c > 0u) {
        if (tid == 0) s_base = atomicAdd(&g_cnt, c);
        __syncthreads();
        unsigned gb = s_base;
        for (unsigned j = tid; j < c; j += bs) g_keys[gb + j] = stage[j];
    }
    __syncthreads();
    for (int i = tid; i < 4096; i += bs) {
        unsigned hv = hist[i];
        if (hv) atomicAdd(&g_hist1[i], hv);
    }
}

// ---------------------------------------------------------------------------
// Pass B: plain refinement scan, bits 19:8 among keys with (key>>20)==p1.
__global__ void passB_kernel() {
    __shared__ unsigned hist[4096];
    const int tid = threadIdx.x, bs = blockDim.x;
    for (int i = tid; i < 4096; i += bs) hist[i] = 0u;
    __syncthreads();

    const unsigned cnt = g_cnt;
    const unsigned p1  = g_p1;
    const uint4* k4 = (const uint4*)g_keys;
    const unsigned m4 = cnt >> 2;
    const unsigned S = gridDim.x * bs;
    unsigned i = blockIdx.x * bs + tid;

#define PROC(u) do {                                              \
        if (((u).x >> 20) == p1) atomicAdd(&hist[((u).x >> 8) & 0xFFFu], 1u); \
        if (((u).y >> 20) == p1) atomicAdd(&hist[((u).y >> 8) & 0xFFFu], 1u); \
        if (((u).z >> 20) == p1) atomicAdd(&hist[((u).z >> 8) & 0xFFFu], 1u); \
        if (((u).w >> 20) == p1) atomicAdd(&hist[((u).w >> 8) & 0xFFFu], 1u); } while (0)
    for (; i + S < m4; i += 2u * S) {
        uint4 a = k4[i], b = k4[i + S];
        PROC(a); PROC(b);
    }
    for (; i < m4; i += S) { uint4 a = k4[i]; PROC(a); }
#undef PROC
    if (blockIdx.x == 0) {
        for (unsigned j = (m4 << 2) + tid; j < cnt; j += bs) {
            unsigned u = g_keys[j];
            if ((u >> 20) == p1) atomicAdd(&hist[(u >> 8) & 0xFFFu], 1u);
        }
    }
    __syncthreads();
    for (int i2 = tid; i2 < 4096; i2 += bs) {
        unsigned hv = hist[i2];
        if (hv) atomicAdd(&g_hist2[i2], hv);
    }
}

// ---------------------------------------------------------------------------
// Pass C: plain refinement scan, bits 7:0 among keys with (key>>8)==p2.
__global__ void passC_kernel() {
    __shared__ unsigned hist[256];
    const int tid = threadIdx.x, bs = blockDim.x;
    if (tid < 256) hist[tid] = 0u;
    __syncthreads();

    const unsigned cnt = g_cnt;
    const unsigned p2  = g_p2;
    const uint4* k4 = (const uint4*)g_keys;
    const unsigned m4 = cnt >> 2;
    const unsigned S = gridDim.x * bs;
    unsigned i = blockIdx.x * bs + tid;

#define PROC(u) do {                                              \
        if (((u).x >> 8) == p2) atomicAdd(&hist[(u).x & 0xFFu], 1u); \
        if (((u).y >> 8) == p2) atomicAdd(&hist[(u).y & 0xFFu], 1u); \
        if (((u).z >> 8) == p2) atomicAdd(&hist[(u).z & 0xFFu], 1u); \
        if (((u).w >> 8) == p2) atomicAdd(&hist[(u).w & 0xFFu], 1u); } while (0)
    for (; i + S < m4; i += 2u * S) {
        uint4 a = k4[i], b = k4[i + S];
        PROC(a); PROC(b);
    }
    for (; i < m4; i += S) { uint4 a = k4[i]; PROC(a); }
#undef PROC
    if (blockIdx.x == 0) {
        for (unsigned j = (m4 << 2) + tid; j < cnt; j += bs) {
            unsigned u = g_keys[j];
            if ((u >> 8) == p2) atomicAdd(&hist[u & 0xFFu], 1u);
        }
    }
    __syncthreads();
    if (tid < 256) {
        unsigned hv = hist[tid];
        if (hv) atomicAdd(&g_hist3[tid], hv);
    }
}

// ---------------------------------------------------------------------------
// Single-block select (1024 threads, 4 bins each): suffix sums + rank locate.
__global__ void select_kernel(int stage) {
    __shared__ unsigned smW[32];
    __shared__ unsigned smE[32];
    __shared__ unsigned sTotal;

    const int tid  = threadIdx.x;
    const int lane = tid & 31;
    const int wid  = tid >> 5;

    const unsigned* hist = (stage == 0) ? g_hist1 : (stage == 1) ? g_hist2 : g_hist3;
    const int nbins      = (stage == 2) ? 256 : 4096;

    unsigned h0 = 0, h1 = 0, h2 = 0, h3 = 0;
    int b0 = tid * 4;
    if (b0 + 0 < nbins) h0 = hist[b0 + 0];
    if (b0 + 1 < nbins) h1 = hist[b0 + 1];
    if (b0 + 2 < nbins) h2 = hist[b0 + 2];
    if (b0 + 3 < nbins) h3 = hist[b0 + 3];
    unsigned s = h0 + h1 + h2 + h3;

    unsigned v = s;
#pragma unroll
    for (int d = 1; d < 32; d <<= 1) {
        unsigned u = __shfl_down_sync(0xffffffffu, v, d);
        if (lane + d < 32) v += u;
    }
    if (lane == 0) smW[wid] = v;
    __syncthreads();
    if (wid == 0) {
        unsigned wv = smW[lane];
        unsigned wi = wv;
#pragma unroll
        for (int d = 1; d < 32; d <<= 1) {
            unsigned u = __shfl_down_sync(0xffffffffu, wi, d);
            if (lane + d < 32) wi += u;
        }
        smE[lane] = wi - wv;
        if (lane == 0) sTotal = wi;
    }
    __syncthreads();
    unsigned sfx = v + smE[wid];

    if (tid == 0) {
        if (stage == 0) {
            unsigned kk = g_k0;
            g_mode = (kk == 0u) ? 1 : (kk > sTotal ? 2 : 0);
            g_p1 = 0u; g_k1 = 0u;
        } else if (stage == 1) {
            g_p2 = 0u; g_k2 = 0u;
        } else {
            int m = g_mode;
            if (m == 1) g_thr = __int_as_float(0x7f800000);  // +inf: keep all
            else if (m == 2) g_thr = 0.0f;                   // drop all negs
        }
    }
    if (stage == 0) { for (int i = tid; i < 4096; i += blockDim.x) g_hist2[i] = 0u; }
    if (stage == 1) { if (tid < 256) g_hist3[tid] = 0u; }
    __syncthreads();

    int mode = g_mode;
    if (stage == 0) mode = (g_k0 == 0u) ? 1 : (g_k0 > sTotal ? 2 : 0);
    unsigned kk = (stage == 0) ? g_k0 : (stage == 1) ? g_k1 : g_k2;
    if (mode != 0 || kk == 0u) return;

    unsigned run = sfx;
    unsigned hh[4] = {h0, h1, h2, h3};
#pragma unroll
    for (int j = 0; j < 4; j++) {
        int bin = b0 + j;
        if (bin < nbins) {
            unsigned next = run - hh[j];
            if (run >= kk && next < kk) {
                if (stage == 0)      { g_p1 = (unsigned)bin;                g_k1 = kk - next; }
                else if (stage == 1) { g_p2 = (g_p1 << 12) | (unsigned)bin; g_k2 = kk - next; }
                else {
                    unsigned key = (g_p2 << 8) | (unsigned)bin;
                    g_thr = neg_loss_f(key2f(key));
                }
            }
            run = next;
        }
    }
}

// ---------------------------------------------------------------------------
__device__ __forceinline__ float lane_loss(float x, unsigned cls, float thr) {
    float ax  = fabsf(x);
    float lse = log1pf(expf(-ax));
    float pl  = fmaxf(-x, 0.0f) + lse;
    float nl  = fmaxf( x, 0.0f) + lse;
    float r = 0.0f;
    if (cls == 1u) r = pl;
    else if (cls == 2u) r = (nl < thr) ? nl : 0.0f;
    return r;
}
__device__ __forceinline__ float elem_loss_t(float x, float t, float thr) {
    unsigned cls = (t > 0.f) ? 1u : ((t < 0.f) ? 2u : 0u);
    return lane_loss(x, cls, thr);
}

__global__ void finalize_kernel(const float* __restrict__ in,
                                const float* __restrict__ tg,
                                float* __restrict__ out, int n) {
    const float thr = g_thr;
    const float4* in4 = (const float4*)in;
    float4* o4 = (float4*)out;
    const int n4 = n >> 2;
    const int S = gridDim.x * blockDim.x;
    int i = blockIdx.x * blockDim.x + threadIdx.x;

    for (; i + S < n4; i += 2 * S) {
        float4 x0 = in4[i];
        float4 x1 = in4[i + S];
        unsigned c0 = g_code[i];
        unsigned c1 = g_code[i + S];
        float4 o0, o1;
        o0.x = lane_loss(x0.x,  c0        & 3u, thr);
        o0.y = lane_loss(x0.y, (c0 >> 2)  & 3u, thr);
        o0.z = lane_loss(x0.z, (c0 >> 4)  & 3u, thr);
        o0.w = lane_loss(x0.w, (c0 >> 6)  & 3u, thr);
        o1.x = lane_loss(x1.x,  c1        & 3u, thr);
        o1.y = lane_loss(x1.y, (c1 >> 2)  & 3u, thr);
        o1.z = lane_loss(x1.z, (c1 >> 4)  & 3u, thr);
        o1.w = lane_loss(x1.w, (c1 >> 6)  & 3u, thr);
        o4[i] = o0;
        o4[i + S] = o1;
    }
    for (; i < n4; i += S) {
        float4 x0 = in4[i];
        unsigned c0 = g_code[i];
        float4 o0;
        o0.x = lane_loss(x0.x,  c0        & 3u, thr);
        o0.y = lane_loss(x0.y, (c0 >> 2)  & 3u, thr);
        o0.z = lane_loss(x0.z, (c0 >> 4)  & 3u, thr);
        o0.w = lane_loss(x0.w, (c0 >> 6)  & 3u, thr);
        o4[i] = o0;
    }
    if (blockIdx.x == 0) {
        for (int j = (n4 << 2) + threadIdx.x; j < n; j += blockDim.x)
            out[j] = elem_loss_t(in[j], tg[j], thr);
    }
}

// ---------------------------------------------------------------------------
extern "C" void kernel_launch(void* const* d_in, const int* in_sizes, int n_in,
                              void* d_out, int out_size) {
    const float* inp  = (const float*)d_in[0];
    const float* tgt  = (const float*)d_in[1];
    const int*   kptr = (const int*)d_in[2];
    float* out = (float*)d_out;
    const int n = in_sizes[0];

    init_kernel<<<1, 1024>>>(kptr);
    passA_kernel<<<1184, 256>>>(inp, tgt, n);
    select_kernel<<<1, 1024>>>(0);
    passB_kernel<<<1184, 256>>>();
    select_kernel<<<1, 1024>>>(1);
    passC_kernel<<<1184, 256>>>();
    select_kernel<<<1, 1024>>>(2);
    finalize_kernel<<<1184, 256>>>(inp, tgt, out, n);
}